// round 1
// baseline (speedup 1.0000x reference)
#include <cuda_runtime.h>
#include <stdint.h>

// Problem constants
#define NN    65536      // total nodes
#define BG    32         // graphs
#define NPG   2048       // nodes per graph
#define ECNT  1048576    // edges
#define FIN   128
#define DLAT  32
#define TOT   97
#define KPHI  30
#define OUTD  32

// ---------------- device scratch (static allocation only) ----------------
__device__ int   g_rowptr[NN + 1];
__device__ int   g_cur[NN];
__device__ int   g_col[ECNT];
__device__ float g_z [NN * DLAT];     // GEMM output buffer
__device__ float g_c0[NN * DLAT];
__device__ float g_c1[NN * DLAT];
__device__ float g_c2[NN * DLAT];
__device__ float g_c3[NN];
__device__ float g_gsum[BG * 32];     // per-graph phi sums (30 used)

// ---------------- helpers ----------------
__device__ __forceinline__ float fast_tanh(float x) {
    float e;
    asm("ex2.approx.f32 %0, %1;" : "=f"(e) : "f"(x * 2.8853900817779268f)); // e = exp(2x)
    float r;
    asm("rcp.approx.f32 %0, %1;" : "=f"(r) : "f"(e + 1.0f));
    return 1.0f - 2.0f * r;
}
__device__ __forceinline__ float fast_rcp(float x) {
    float r;
    asm("rcp.approx.f32 %0, %1;" : "=f"(r) : "f"(x));
    return r;
}

// ---------------- CSR build ----------------
// One block, 1024 threads; each owns 64 consecutive nodes.
__global__ void build_rowptr_kernel(const float* __restrict__ degs) {
    __shared__ int s[1024];
    int t = threadIdx.x;
    int base = t * 64;
    int sum = 0;
    for (int i = 0; i < 64; i++)
        sum += (int)(degs[base + i] + 0.5f) - 1;   // node_degs = indeg + 1
    s[t] = sum;
    __syncthreads();
    // Hillis-Steele inclusive scan
    for (int off = 1; off < 1024; off <<= 1) {
        int v = 0;
        if (t >= off) v = s[t - off];
        __syncthreads();
        if (t >= off) s[t] += v;
        __syncthreads();
    }
    int running = (t == 0) ? 0 : s[t - 1];
    for (int i = 0; i < 64; i++) {
        g_rowptr[base + i] = running;
        g_cur[base + i]    = running;
        running += (int)(degs[base + i] + 0.5f) - 1;
    }
    if (t == 1023) g_rowptr[NN] = running;
    // zero per-graph accumulators (exactly 1024 entries)
    g_gsum[t] = 0.0f;
}

__global__ void fill_csr_kernel(const int* __restrict__ ei) {
    int e = blockIdx.x * blockDim.x + threadIdx.x;
    if (e >= ECNT) return;
    int s = ei[e];
    int d = ei[ECNT + e];
    int pos = atomicAdd(&g_cur[d], 1);
    g_col[pos] = s;
}

// ---------------- GEMM: Z[N,32] = X[N,K] @ W[K,32] ----------------
// block = 256 threads, 32 rows/block, each thread: 1 row x 4 cols
template<int K>
__global__ void gemm32_kernel(const float* __restrict__ X, const float* __restrict__ W,
                              float* __restrict__ Z) {
    __shared__ float Ws[K * 32];
    __shared__ float Xs[32][K + 1];
    int tid  = threadIdx.x;
    int base = blockIdx.x * 32;
    for (int i = tid; i < K * 32; i += 256) Ws[i] = W[i];
    for (int i = tid; i < 32 * K; i += 256) {
        int r = i / K, c = i % K;
        Xs[r][c] = X[(base + r) * K + c];
    }
    __syncthreads();
    int row  = tid >> 3;
    int colg = (tid & 7) * 4;
    float a0 = 0.f, a1 = 0.f, a2 = 0.f, a3 = 0.f;
#pragma unroll 8
    for (int k = 0; k < K; k++) {
        float  x = Xs[row][k];
        float4 w = *(const float4*)&Ws[k * 32 + colg];
        a0 += x * w.x; a1 += x * w.y; a2 += x * w.z; a3 += x * w.w;
    }
    *(float4*)&Z[(base + row) * 32 + colg] = make_float4(a0, a1, a2, a3);
}

// ---------------- GEMM 32 -> 1 ----------------
__global__ void gemm1_kernel(const float* __restrict__ X, const float* __restrict__ W3,
                             float* __restrict__ z1) {
    __shared__ float Xs[256][33];
    __shared__ float w[32];
    int tid  = threadIdx.x;
    int base = blockIdx.x * 256;
    if (tid < 32) w[tid] = W3[tid];
    for (int i = tid; i < 256 * 32; i += 256) {
        int r = i >> 5, k = i & 31;
        Xs[r][k] = X[(base + r) * 32 + k];
    }
    __syncthreads();
    float acc = 0.f;
#pragma unroll
    for (int k = 0; k < 32; k++) acc += Xs[tid][k] * w[k];
    z1[base + tid] = acc;
}

// ---------------- aggregation width 32: out = tanh((spmm(z)+z+b)/deg) ----------------
// warp per node, lane per feature; CSR gather (coalesced 128B reads per edge)
__global__ void agg32_kernel(const float* __restrict__ z, const float* __restrict__ b,
                             const float* __restrict__ degs, float* __restrict__ out) {
    int warp = (blockIdx.x * blockDim.x + threadIdx.x) >> 5;
    int lane = threadIdx.x & 31;
    if (warp >= NN) return;
    int   i   = warp;
    float acc = z[i * 32 + lane];
    int   s = g_rowptr[i], e = g_rowptr[i + 1];
    int   j = s;
    // unroll-by-4 to expose MLP
    for (; j + 4 <= e; j += 4) {
        int c0 = g_col[j], c1 = g_col[j + 1], c2 = g_col[j + 2], c3 = g_col[j + 3];
        float v0 = z[c0 * 32 + lane];
        float v1 = z[c1 * 32 + lane];
        float v2 = z[c2 * 32 + lane];
        float v3 = z[c3 * 32 + lane];
        acc += v0 + v1 + v2 + v3;
    }
    for (; j < e; j++) acc += z[g_col[j] * 32 + lane];
    float rinv = fast_rcp(degs[i]);
    out[i * 32 + lane] = fast_tanh((acc + b[lane]) * rinv);
}

// ---------------- aggregation width 1 ----------------
__global__ void agg1_kernel(const float* __restrict__ z1, const float* __restrict__ b3,
                            const float* __restrict__ degs, float* __restrict__ out) {
    int i = blockIdx.x * blockDim.x + threadIdx.x;
    if (i >= NN) return;
    float acc = z1[i];
    int s = g_rowptr[i], e = g_rowptr[i + 1];
    int j = s;
    for (; j + 4 <= e; j += 4) {
        float v0 = z1[g_col[j]];
        float v1 = z1[g_col[j + 1]];
        float v2 = z1[g_col[j + 2]];
        float v3 = z1[g_col[j + 3]];
        acc += v0 + v1 + v2 + v3;
    }
    for (; j < e; j++) acc += z1[g_col[j]];
    float rinv = fast_rcp(degs[i]);
    out[i] = fast_tanh((acc + b3[0]) * rinv);
}

// ---------------- phi + per-graph reduction ----------------
// block = 256 threads = 8 node-slots x 32 lanes (lane = phi output, 30 active)
// each block handles 256 nodes of exactly one graph (2048/256 = 8 blocks/graph)
__global__ void phi_kernel(const float* __restrict__ c0, const float* __restrict__ c1,
                           const float* __restrict__ c2, const float* __restrict__ c3,
                           const float* __restrict__ phiW, const float* __restrict__ phib) {
    __shared__ float Wp[TOT * KPHI];   // 97*30
    __shared__ float Ms[8][TOT];
    __shared__ float bs[32];
    __shared__ float Ps[256];
    int tid    = threadIdx.x;
    int slot   = tid >> 5;
    int lane   = tid & 31;
    int g_base = blockIdx.x * 256;

    for (int i = tid; i < TOT * KPHI; i += 256) Wp[i] = phiW[i];
    if (tid < KPHI) bs[tid] = phib[tid];

    float part = 0.f;
    for (int it = 0; it < 32; it++) {
        int nb = g_base + it * 8;
        __syncthreads();
        {
            int r = tid >> 5, k = tid & 31;
            Ms[r][k]      = c0[(nb + r) * 32 + k];
            Ms[r][32 + k] = c1[(nb + r) * 32 + k];
            Ms[r][64 + k] = c2[(nb + r) * 32 + k];
            if (k == 0) Ms[r][96] = c3[nb + r];
        }
        __syncthreads();
        if (lane < KPHI) {
            float acc = bs[lane];
#pragma unroll
            for (int k = 0; k < TOT; k++) acc += Ms[slot][k] * Wp[k * KPHI + lane];
            part += fmaxf(acc, 0.f);
        }
    }
    __syncthreads();
    Ps[tid] = part;
    __syncthreads();
    if (tid < KPHI) {
        float s = 0.f;
#pragma unroll
        for (int q = 0; q < 8; q++) s += Ps[q * 32 + tid];
        atomicAdd(&g_gsum[(g_base / NPG) * 32 + tid], s);
    }
}

// ---------------- rho: out[B,32] = gsum[B,30] @ rhoW[30,32] + rhob ----------------
__global__ void rho_kernel(const float* __restrict__ rhoW, const float* __restrict__ rhob,
                           float* __restrict__ out) {
    int t = threadIdx.x;            // 1024 = 32 graphs x 32 outputs
    int g = t >> 5, o = t & 31;
    float acc = rhob[o];
#pragma unroll
    for (int k = 0; k < KPHI; k++) acc += g_gsum[g * 32 + k] * rhoW[k * 32 + o];
    out[t] = acc;
}

// ---------------- launch ----------------
extern "C" void kernel_launch(void* const* d_in, const int* in_sizes, int n_in,
                              void* d_out, int out_size) {
    const float *node_feat, *node_degs;
    const int*   edge_index;
    const float *W0, *b0, *W1, *b1, *W2, *b2, *W3, *b3, *phiW, *phib, *rhoW, *rhob;

    if (in_sizes[2] == 2 * ECNT) {
        // dict order: node_feat, node_degs, edge_index, W0,b0,...,rho_b
        node_feat  = (const float*)d_in[0];
        node_degs  = (const float*)d_in[1];
        edge_index = (const int*)  d_in[2];
        W0 = (const float*)d_in[3];  b0 = (const float*)d_in[4];
        W1 = (const float*)d_in[5];  b1 = (const float*)d_in[6];
        W2 = (const float*)d_in[7];  b2 = (const float*)d_in[8];
        W3 = (const float*)d_in[9];  b3 = (const float*)d_in[10];
        phiW = (const float*)d_in[11]; phib = (const float*)d_in[12];
        rhoW = (const float*)d_in[13]; rhob = (const float*)d_in[14];
    } else {
        // signature order: node_feat, node_degs, W0,b0,...,rho_b, edge_index
        node_feat  = (const float*)d_in[0];
        node_degs  = (const float*)d_in[1];
        W0 = (const float*)d_in[2];  b0 = (const float*)d_in[3];
        W1 = (const float*)d_in[4];  b1 = (const float*)d_in[5];
        W2 = (const float*)d_in[6];  b2 = (const float*)d_in[7];
        W3 = (const float*)d_in[8];  b3 = (const float*)d_in[9];
        phiW = (const float*)d_in[10]; phib = (const float*)d_in[11];
        rhoW = (const float*)d_in[12]; rhob = (const float*)d_in[13];
        edge_index = (const int*)d_in[14];
    }

    float* zbuf;  cudaGetSymbolAddress((void**)&zbuf,  g_z);
    float* c0b;   cudaGetSymbolAddress((void**)&c0b,   g_c0);
    float* c1b;   cudaGetSymbolAddress((void**)&c1b,   g_c1);
    float* c2b;   cudaGetSymbolAddress((void**)&c2b,   g_c2);
    float* c3b;   cudaGetSymbolAddress((void**)&c3b,   g_c3);

    // CSR build (reused by all 4 layers)
    build_rowptr_kernel<<<1, 1024>>>(node_degs);
    fill_csr_kernel<<<ECNT / 512, 512>>>(edge_index);

    // layer 0: 128 -> 32
    gemm32_kernel<FIN><<<NN / 32, 256>>>(node_feat, W0, zbuf);
    agg32_kernel<<<NN / 8, 256>>>(zbuf, b0, node_degs, c0b);
    // layer 1: 32 -> 32
    gemm32_kernel<DLAT><<<NN / 32, 256>>>(c0b, W1, zbuf);
    agg32_kernel<<<NN / 8, 256>>>(zbuf, b1, node_degs, c1b);
    // layer 2: 32 -> 32
    gemm32_kernel<DLAT><<<NN / 32, 256>>>(c1b, W2, zbuf);
    agg32_kernel<<<NN / 8, 256>>>(zbuf, b2, node_degs, c2b);
    // layer 3: 32 -> 1
    gemm1_kernel<<<NN / 256, 256>>>(c2b, W3, zbuf);
    agg1_kernel<<<NN / 256, 256>>>(zbuf, b3, node_degs, c3b);

    // DeepSets
    phi_kernel<<<NN / 256, 256>>>(c0b, c1b, c2b, c3b, phiW, phib);
    rho_kernel<<<1, 1024>>>(rhoW, rhob, (float*)d_out);
}

// round 2
// speedup vs baseline: 1.9326x; 1.9326x over previous
#include <cuda_runtime.h>
#include <stdint.h>

#define NN    65536
#define BG    32
#define NPG   2048
#define ECNT  1048576
#define FIN   128
#define DLAT  32
#define TOT   97
#define KPHI  30
#define SLOT  64        // adjacency capacity per node (P(deg>64) ~ 1e-19)

// ---------------- device scratch ----------------
__device__ int   g_cnt[NN];
__device__ int   g_col[NN * SLOT];
__device__ float g_z  [NN * DLAT];
__device__ float g_z2 [NN * DLAT];
__device__ float g_c0 [NN * DLAT];
__device__ float g_c1 [NN * DLAT];
__device__ float g_c2 [NN * DLAT];
__device__ float g_z1 [NN];
__device__ float g_gsum[BG * 32];

// ---------------- helpers ----------------
__device__ __forceinline__ float fast_tanh(float x) {
    float e;
    asm("ex2.approx.f32 %0, %1;" : "=f"(e) : "f"(x * 2.8853900817779268f));
    float r;
    asm("rcp.approx.f32 %0, %1;" : "=f"(r) : "f"(e + 1.0f));
    return 1.0f - 2.0f * r;
}
__device__ __forceinline__ float fast_rcp(float x) {
    float r;
    asm("rcp.approx.f32 %0, %1;" : "=f"(r) : "f"(x));
    return r;
}

// ---------------- init: zero counters + graph sums ----------------
__global__ void zero_kernel() {
    int t = blockIdx.x * blockDim.x + threadIdx.x;
    if (t < NN) g_cnt[t] = 0;
    if (t < BG * 32) g_gsum[t] = 0.0f;
}

// ---------------- adjacency fill (slotted, no rowptr) ----------------
__global__ void fill_adj_kernel(const int* __restrict__ ei) {
    int e = blockIdx.x * blockDim.x + threadIdx.x;
    if (e >= ECNT) return;
    int s = ei[e];
    int d = ei[ECNT + e];
    int pos = atomicAdd(&g_cnt[d], 1);
    g_col[d * SLOT + pos] = s;
}

// ---------------- GEMM: Z[N,32] = X[N,128] @ W0[128,32] ----------------
__global__ void gemm128_kernel(const float* __restrict__ X, const float* __restrict__ W,
                               float* __restrict__ Z) {
    __shared__ float Ws[FIN * 32];
    __shared__ float Xs[32][FIN + 1];
    int tid  = threadIdx.x;
    int base = blockIdx.x * 32;
    for (int i = tid; i < FIN * 32; i += 256) Ws[i] = W[i];
    for (int i = tid; i < 32 * FIN; i += 256) {
        int r = i >> 7, c = i & 127;
        Xs[r][c] = X[(base + r) * FIN + c];
    }
    __syncthreads();
    int row  = tid >> 3;
    int colg = (tid & 7) * 4;
    float a0 = 0.f, a1 = 0.f, a2 = 0.f, a3 = 0.f;
#pragma unroll 8
    for (int k = 0; k < FIN; k++) {
        float  x = Xs[row][k];
        float4 w = *(const float4*)&Ws[k * 32 + colg];
        a0 += x * w.x; a1 += x * w.y; a2 += x * w.z; a3 += x * w.w;
    }
    *(float4*)&Z[(base + row) * 32 + colg] = make_float4(a0, a1, a2, a3);
}

// ---------------- gather core (warp per node, lane per feature) ----------------
__device__ __forceinline__ float gather_acc32(const float* __restrict__ z, int node,
                                              int deg, int lane) {
    float acc = z[node * 32 + lane];
    int base = node * SLOT;
    int j = 0;
    for (; j + 8 <= deg; j += 8) {
        int4 a = *(const int4*)&g_col[base + j];
        int4 b = *(const int4*)&g_col[base + j + 4];
        float v0 = z[a.x * 32 + lane];
        float v1 = z[a.y * 32 + lane];
        float v2 = z[a.z * 32 + lane];
        float v3 = z[a.w * 32 + lane];
        float v4 = z[b.x * 32 + lane];
        float v5 = z[b.y * 32 + lane];
        float v6 = z[b.z * 32 + lane];
        float v7 = z[b.w * 32 + lane];
        acc += ((v0 + v1) + (v2 + v3)) + ((v4 + v5) + (v6 + v7));
    }
    if (j + 4 <= deg) {
        int4 a = *(const int4*)&g_col[base + j];
        acc += (z[a.x * 32 + lane] + z[a.y * 32 + lane])
             + (z[a.z * 32 + lane] + z[a.w * 32 + lane]);
        j += 4;
    }
    for (; j < deg; j++) acc += z[g_col[base + j] * 32 + lane];
    return acc;
}

// ---------------- agg + tanh + fused next GEMM (32->32) ----------------
__global__ void agg_gemm32_kernel(const float* __restrict__ z, const float* __restrict__ b,
                                  const float* __restrict__ Wn, const float* __restrict__ degs,
                                  float* __restrict__ c_out, float* __restrict__ z_out) {
    __shared__ float Wsm[32 * 32];
    __shared__ float bsm[32];
    int tid = threadIdx.x;
    for (int i = tid; i < 1024; i += 256) Wsm[i] = Wn[i];
    if (tid < 32) bsm[tid] = b[tid];
    __syncthreads();

    int warp = (blockIdx.x * blockDim.x + tid) >> 5;
    int lane = tid & 31;
    if (warp >= NN) return;
    float dv  = degs[warp];
    int   deg = (int)(dv + 0.5f) - 1;
    float acc = gather_acc32(z, warp, deg, lane);
    float h   = fast_tanh((acc + bsm[lane]) * fast_rcp(dv));
    c_out[warp * 32 + lane] = h;

    float zn = 0.f;
#pragma unroll
    for (int k = 0; k < 32; k++)
        zn += __shfl_sync(0xffffffffu, h, k) * Wsm[k * 32 + lane];
    z_out[warp * 32 + lane] = zn;
}

// ---------------- agg + tanh + fused 32->1 GEMM (layer 2) ----------------
__global__ void agg_gemm1_kernel(const float* __restrict__ z, const float* __restrict__ b,
                                 const float* __restrict__ W3, const float* __restrict__ degs,
                                 float* __restrict__ c_out, float* __restrict__ z1_out) {
    __shared__ float w3[32];
    __shared__ float bsm[32];
    int tid = threadIdx.x;
    if (tid < 32) { w3[tid] = W3[tid]; bsm[tid] = b[tid]; }
    __syncthreads();

    int warp = (blockIdx.x * blockDim.x + tid) >> 5;
    int lane = tid & 31;
    if (warp >= NN) return;
    float dv  = degs[warp];
    int   deg = (int)(dv + 0.5f) - 1;
    float acc = gather_acc32(z, warp, deg, lane);
    float h   = fast_tanh((acc + bsm[lane]) * fast_rcp(dv));
    c_out[warp * 32 + lane] = h;

    float v = h * w3[lane];
#pragma unroll
    for (int off = 16; off; off >>= 1) v += __shfl_xor_sync(0xffffffffu, v, off);
    if (lane == 0) z1_out[warp] = v;
}

// ---------------- fused: agg width-1 (layer 3) + phi + per-graph reduce ----------------
// block = 256 threads = 256 nodes (one 8th of a graph)
__global__ void agg1_phi_kernel(const float* __restrict__ z1, const float* __restrict__ b3,
                                const float* __restrict__ degs,
                                const float* __restrict__ c0, const float* __restrict__ c1,
                                const float* __restrict__ c2,
                                const float* __restrict__ phiW, const float* __restrict__ phib) {
    __shared__ float Msm[64 * 100];      // 64 nodes x 97 feats (pad 100)
    __shared__ float Wt[30 * 100];       // phiW transposed [out][k], pad 100
    __shared__ float c3s[256];
    __shared__ float bs[32];
    __shared__ float red[8 * 32];

    int tid  = threadIdx.x;
    int lane = tid & 31;
    int wrp  = tid >> 5;
    int nblk = blockIdx.x * 256;

    // stage transposed phi weights
    for (int i = tid; i < TOT * KPHI; i += 256) {
        int k = i / KPHI, o = i - k * KPHI;
        Wt[o * 100 + k] = phiW[i];
    }
    if (tid < KPHI) bs[tid] = phib[tid];

    // layer-3 aggregation: thread per node
    {
        int   n   = nblk + tid;
        float dv  = degs[n];
        int   deg = (int)(dv + 0.5f) - 1;
        float acc = z1[n];
        int base = n * SLOT;
        int j = 0;
        for (; j + 4 <= deg; j += 4) {
            int4 a = *(const int4*)&g_col[base + j];
            acc += (z1[a.x] + z1[a.y]) + (z1[a.z] + z1[a.w]);
        }
        for (; j < deg; j++) acc += z1[g_col[base + j]];
        c3s[tid] = fast_tanh((acc + b3[0]) * fast_rcp(dv));
    }

    float psum = 0.f;   // per-lane (=output) running sum over this thread's warp-nodes

    for (int it = 0; it < 4; it++) {
        int nb = nblk + it * 64;
        __syncthreads();
        for (int i = tid; i < 64 * 32; i += 256) {
            int r = i >> 5, k = i & 31;
            Msm[r * 100 + k]      = c0[(nb + r) * 32 + k];
            Msm[r * 100 + 32 + k] = c1[(nb + r) * 32 + k];
            Msm[r * 100 + 64 + k] = c2[(nb + r) * 32 + k];
        }
        if (tid < 64) Msm[tid * 100 + 96] = c3s[it * 64 + tid];
        __syncthreads();

        // warp handles 8 nodes (rows wrp*8 .. wrp*8+7), lane = phi output
        float a0=0,a1=0,a2=0,a3=0,a4=0,a5=0,a6=0,a7=0;
        const float* Mr = &Msm[(wrp * 8) * 100];
        if (lane < KPHI) {
            const float* wrow = &Wt[lane * 100];
#pragma unroll 4
            for (int kk = 0; kk < 96; kk += 4) {
                float4 w = *(const float4*)&wrow[kk];
                float4 m0 = *(const float4*)&Mr[0 * 100 + kk];
                float4 m1 = *(const float4*)&Mr[1 * 100 + kk];
                float4 m2 = *(const float4*)&Mr[2 * 100 + kk];
                float4 m3 = *(const float4*)&Mr[3 * 100 + kk];
                float4 m4 = *(const float4*)&Mr[4 * 100 + kk];
                float4 m5 = *(const float4*)&Mr[5 * 100 + kk];
                float4 m6 = *(const float4*)&Mr[6 * 100 + kk];
                float4 m7 = *(const float4*)&Mr[7 * 100 + kk];
                a0 += m0.x*w.x + m0.y*w.y + m0.z*w.z + m0.w*w.w;
                a1 += m1.x*w.x + m1.y*w.y + m1.z*w.z + m1.w*w.w;
                a2 += m2.x*w.x + m2.y*w.y + m2.z*w.z + m2.w*w.w;
                a3 += m3.x*w.x + m3.y*w.y + m3.z*w.z + m3.w*w.w;
                a4 += m4.x*w.x + m4.y*w.y + m4.z*w.z + m4.w*w.w;
                a5 += m5.x*w.x + m5.y*w.y + m5.z*w.z + m5.w*w.w;
                a6 += m6.x*w.x + m6.y*w.y + m6.z*w.z + m6.w*w.w;
                a7 += m7.x*w.x + m7.y*w.y + m7.z*w.z + m7.w*w.w;
            }
            float w96 = wrow[96];
            float bb  = bs[lane];
            a0 += Mr[0*100+96]*w96; a1 += Mr[1*100+96]*w96;
            a2 += Mr[2*100+96]*w96; a3 += Mr[3*100+96]*w96;
            a4 += Mr[4*100+96]*w96; a5 += Mr[5*100+96]*w96;
            a6 += Mr[6*100+96]*w96; a7 += Mr[7*100+96]*w96;
            psum += fmaxf(a0+bb,0.f)+fmaxf(a1+bb,0.f)+fmaxf(a2+bb,0.f)+fmaxf(a3+bb,0.f)
                  + fmaxf(a4+bb,0.f)+fmaxf(a5+bb,0.f)+fmaxf(a6+bb,0.f)+fmaxf(a7+bb,0.f);
        }
    }

    __syncthreads();
    red[wrp * 32 + lane] = psum;
    __syncthreads();
    if (tid < KPHI) {
        float s = 0.f;
#pragma unroll
        for (int q = 0; q < 8; q++) s += red[q * 32 + tid];
        atomicAdd(&g_gsum[(blockIdx.x >> 3) * 32 + tid], s);
    }
}

// ---------------- rho ----------------
__global__ void rho_kernel(const float* __restrict__ rhoW, const float* __restrict__ rhob,
                           float* __restrict__ out) {
    int t = threadIdx.x;
    int g = t >> 5, o = t & 31;
    float acc = rhob[o];
#pragma unroll
    for (int k = 0; k < KPHI; k++) acc += g_gsum[g * 32 + k] * rhoW[k * 32 + o];
    out[t] = acc;
}

// ---------------- launch ----------------
extern "C" void kernel_launch(void* const* d_in, const int* in_sizes, int n_in,
                              void* d_out, int out_size) {
    const float *node_feat, *node_degs;
    const int*   edge_index;
    const float *W0, *b0, *W1, *b1, *W2, *b2, *W3, *b3, *phiW, *phib, *rhoW, *rhob;

    if (in_sizes[2] == 2 * ECNT) {
        node_feat  = (const float*)d_in[0];
        node_degs  = (const float*)d_in[1];
        edge_index = (const int*)  d_in[2];
        W0 = (const float*)d_in[3];  b0 = (const float*)d_in[4];
        W1 = (const float*)d_in[5];  b1 = (const float*)d_in[6];
        W2 = (const float*)d_in[7];  b2 = (const float*)d_in[8];
        W3 = (const float*)d_in[9];  b3 = (const float*)d_in[10];
        phiW = (const float*)d_in[11]; phib = (const float*)d_in[12];
        rhoW = (const float*)d_in[13]; rhob = (const float*)d_in[14];
    } else {
        node_feat  = (const float*)d_in[0];
        node_degs  = (const float*)d_in[1];
        W0 = (const float*)d_in[2];  b0 = (const float*)d_in[3];
        W1 = (const float*)d_in[4];  b1 = (const float*)d_in[5];
        W2 = (const float*)d_in[6];  b2 = (const float*)d_in[7];
        W3 = (const float*)d_in[8];  b3 = (const float*)d_in[9];
        phiW = (const float*)d_in[10]; phib = (const float*)d_in[11];
        rhoW = (const float*)d_in[12]; rhob = (const float*)d_in[13];
        edge_index = (const int*)d_in[14];
    }

    float *zb, *z2b, *c0b, *c1b, *c2b, *z1b;
    cudaGetSymbolAddress((void**)&zb,  g_z);
    cudaGetSymbolAddress((void**)&z2b, g_z2);
    cudaGetSymbolAddress((void**)&c0b, g_c0);
    cudaGetSymbolAddress((void**)&c1b, g_c1);
    cudaGetSymbolAddress((void**)&c2b, g_c2);
    cudaGetSymbolAddress((void**)&z1b, g_z1);

    zero_kernel<<<NN / 256, 256>>>();
    fill_adj_kernel<<<ECNT / 512, 512>>>(edge_index);

    // layer 0: z = X @ W0 ; c0 = tanh((A z + z + b0)/deg) ; z2 = c0 @ W1
    gemm128_kernel<<<NN / 32, 256>>>(node_feat, W0, zb);
    agg_gemm32_kernel<<<NN / 8, 256>>>(zb, b0, W1, node_degs, c0b, z2b);
    // layer 1: c1 = tanh((A z2 + z2 + b1)/deg) ; z = c1 @ W2
    agg_gemm32_kernel<<<NN / 8, 256>>>(z2b, b1, W2, node_degs, c1b, zb);
    // layer 2: c2 = tanh((A z + z + b2)/deg) ; z1 = c2 @ W3
    agg_gemm1_kernel<<<NN / 8, 256>>>(zb, b2, W3, node_degs, c2b, z1b);
    // layer 3 + phi + per-graph sum
    agg1_phi_kernel<<<NN / 256, 256>>>(z1b, b3, node_degs, c0b, c1b, c2b, phiW, phib);
    // rho
    rho_kernel<<<1, 1024>>>(rhoW, rhob, (float*)d_out);
}

// round 3
// speedup vs baseline: 2.3542x; 1.2181x over previous
#include <cuda_runtime.h>
#include <cuda_fp16.h>
#include <stdint.h>

#define NN    65536
#define BG    32
#define NPG   2048
#define ECNT  1048576
#define FIN   128
#define DLAT  32
#define TOT   97
#define KPHI  30
#define SLOT  64        // adjacency capacity per node

// ---------------- device scratch ----------------
__device__ int   g_cnt[NN];
__device__ int   g_colb[NN * SLOT];     // byte offsets: src*64 (fp16 row stride)
__device__ __half2 g_zha[NN * 16];      // z ping (fp16, 32 feats = 16 half2)
__device__ __half2 g_zhb[NN * 16];      // z pong
__device__ float g_c0 [NN * DLAT];
__device__ float g_c1 [NN * DLAT];
__device__ float g_c2 [NN * DLAT];
__device__ float g_z1 [NN];
__device__ float g_gsum[BG * 32];

// ---------------- helpers ----------------
__device__ __forceinline__ float fast_tanh(float x) {
    float e;
    asm("ex2.approx.f32 %0, %1;" : "=f"(e) : "f"(x * 2.8853900817779268f));
    float r;
    asm("rcp.approx.f32 %0, %1;" : "=f"(r) : "f"(e + 1.0f));
    return 1.0f - 2.0f * r;
}
__device__ __forceinline__ float fast_rcp(float x) {
    float r;
    asm("rcp.approx.f32 %0, %1;" : "=f"(r) : "f"(x));
    return r;
}

// ---------------- init ----------------
__global__ void zero_kernel() {
    int t = blockIdx.x * blockDim.x + threadIdx.x;
    if (t < NN) g_cnt[t] = 0;
    if (t < BG * 32) g_gsum[t] = 0.0f;
}

// ---------------- adjacency fill: store byte offsets of fp16 rows ----------------
__global__ void fill_adj_kernel(const int* __restrict__ ei) {
    int e = blockIdx.x * blockDim.x + threadIdx.x;
    if (e >= ECNT) return;
    int s = ei[e];
    int d = ei[ECNT + e];
    int pos = atomicAdd(&g_cnt[d], 1);
    g_colb[d * SLOT + pos] = s * 64;    // 32 feats * 2B
}

// ---------------- GEMM: Z[N,32](fp16) = X[N,128] @ W0[128,32] ----------------
__global__ void gemm128_kernel(const float* __restrict__ X, const float* __restrict__ W,
                               __half2* __restrict__ Z) {
    __shared__ float Ws[FIN * 32];
    __shared__ float Xs[32][FIN + 1];
    int tid  = threadIdx.x;
    int base = blockIdx.x * 32;
    for (int i = tid; i < FIN * 32; i += 256) Ws[i] = W[i];
    for (int i = tid; i < 32 * FIN; i += 256) {
        int r = i >> 7, c = i & 127;
        Xs[r][c] = X[(base + r) * FIN + c];
    }
    __syncthreads();
    int row  = tid >> 3;
    int colg = (tid & 7) * 4;
    float a0 = 0.f, a1 = 0.f, a2 = 0.f, a3 = 0.f;
#pragma unroll 8
    for (int k = 0; k < FIN; k++) {
        float  x = Xs[row][k];
        float4 w = *(const float4*)&Ws[k * 32 + colg];
        a0 += x * w.x; a1 += x * w.y; a2 += x * w.z; a3 += x * w.w;
    }
    __half2* zr = Z + (base + row) * 16 + (colg >> 1);
    zr[0] = __floats2half2_rn(a0, a1);
    zr[1] = __floats2half2_rn(a2, a3);
}

// ---------------- gather core: half-warp per node, lane-pair features ----------------
// returns float2 = aggregated (self + neighbors) features (2l, 2l+1)
__device__ __forceinline__ float2 gather16(const __half2* __restrict__ zh, int node,
                                           int deg, int l) {
    const char* zb   = (const char*)zh;
    unsigned    loff = (unsigned)(l * 4);
    const int*  col  = &g_colb[node * SLOT];
    __half2 acc0 = *(const __half2*)(zb + (unsigned)(node * 64) + loff);
    __half2 acc1 = __float2half2_rn(0.0f);
    int j = 0;
    for (; j + 4 <= deg; j += 4) {
        int4 o = *(const int4*)(col + j);
        __half2 v0 = *(const __half2*)(zb + (unsigned)o.x + loff);
        __half2 v1 = *(const __half2*)(zb + (unsigned)o.y + loff);
        __half2 v2 = *(const __half2*)(zb + (unsigned)o.z + loff);
        __half2 v3 = *(const __half2*)(zb + (unsigned)o.w + loff);
        acc0 = __hadd2(acc0, v0);
        acc1 = __hadd2(acc1, v1);
        acc0 = __hadd2(acc0, v2);
        acc1 = __hadd2(acc1, v3);
    }
    for (; j < deg; j++) {
        int o = col[j];
        acc0 = __hadd2(acc0, *(const __half2*)(zb + (unsigned)o + loff));
    }
    float2 a = __half22float2(acc0);
    float2 c = __half22float2(acc1);
    return make_float2(a.x + c.x, a.y + c.y);
}

// ---------------- agg + tanh + fused next GEMM (32->32, fp16 out) ----------------
// block 256 = 8 warps = 16 nodes
__global__ void agg_gemm32_kernel(const __half2* __restrict__ zh, const float* __restrict__ b,
                                  const float* __restrict__ Wn, const float* __restrict__ degs,
                                  float* __restrict__ c_out, __half2* __restrict__ z_out) {
    __shared__ float Wsm[32][34];   // W row-major, pairs contiguous, padded
    __shared__ float bsm[32];
    __shared__ float hs[16][33];    // staged h per node slot
    int tid = threadIdx.x;
    for (int i = tid; i < 1024; i += 256) Wsm[i >> 5][i & 31] = Wn[i];
    if (tid < 32) bsm[tid] = b[tid];
    __syncthreads();

    int lane = tid & 31;
    int l    = lane & 15;
    int node = ((blockIdx.x * 256 + tid) >> 5) * 2 + (lane >> 4);
    int slot = ((tid >> 5) << 1) + (lane >> 4);

    float dv  = degs[node];
    int   deg = (int)(dv + 0.5f) - 1;
    float2 acc = gather16(zh, node, deg, l);
    float rinv = fast_rcp(dv);
    float hx = fast_tanh((acc.x + bsm[2 * l])     * rinv);
    float hy = fast_tanh((acc.y + bsm[2 * l + 1]) * rinv);
    *(float2*)&c_out[node * 32 + 2 * l] = make_float2(hx, hy);

    hs[slot][2 * l]     = hx;
    hs[slot][2 * l + 1] = hy;
    __syncwarp();

    float z0 = 0.f, z1v = 0.f;
#pragma unroll
    for (int k = 0; k < 32; k++) {
        float  hk = hs[slot][k];
        float2 w  = *(const float2*)&Wsm[k][2 * l];
        z0  += hk * w.x;
        z1v += hk * w.y;
    }
    z_out[node * 16 + l] = __floats2half2_rn(z0, z1v);
}

// ---------------- agg + tanh + fused 32->1 GEMM (layer 2) ----------------
__global__ void agg_gemm1_kernel(const __half2* __restrict__ zh, const float* __restrict__ b,
                                 const float* __restrict__ W3, const float* __restrict__ degs,
                                 float* __restrict__ c_out, float* __restrict__ z1_out) {
    __shared__ float w3[32];
    __shared__ float bsm[32];
    int tid = threadIdx.x;
    if (tid < 32) { w3[tid] = W3[tid]; bsm[tid] = b[tid]; }
    __syncthreads();

    int lane = tid & 31;
    int l    = lane & 15;
    int node = ((blockIdx.x * 256 + tid) >> 5) * 2 + (lane >> 4);

    float dv  = degs[node];
    int   deg = (int)(dv + 0.5f) - 1;
    float2 acc = gather16(zh, node, deg, l);
    float rinv = fast_rcp(dv);
    float hx = fast_tanh((acc.x + bsm[2 * l])     * rinv);
    float hy = fast_tanh((acc.y + bsm[2 * l + 1]) * rinv);
    *(float2*)&c_out[node * 32 + 2 * l] = make_float2(hx, hy);

    float v = hx * w3[2 * l] + hy * w3[2 * l + 1];
#pragma unroll
    for (int off = 8; off; off >>= 1) v += __shfl_xor_sync(0xffffffffu, v, off);
    if (l == 0) z1_out[node] = v;
}

// ---------------- fused: agg width-1 (layer 3) + phi + per-graph reduce ----------------
__global__ void agg1_phi_kernel(const float* __restrict__ z1, const float* __restrict__ b3,
                                const float* __restrict__ degs,
                                const float* __restrict__ c0, const float* __restrict__ c1,
                                const float* __restrict__ c2,
                                const float* __restrict__ phiW, const float* __restrict__ phib) {
    __shared__ float Msm[64 * 100];
    __shared__ float Wt[30 * 100];
    __shared__ float c3s[256];
    __shared__ float bs[32];
    __shared__ float red[8 * 32];

    int tid  = threadIdx.x;
    int lane = tid & 31;
    int wrp  = tid >> 5;
    int nblk = blockIdx.x * 256;

    for (int i = tid; i < TOT * KPHI; i += 256) {
        int k = i / KPHI, o = i - k * KPHI;
        Wt[o * 100 + k] = phiW[i];
    }
    if (tid < KPHI) bs[tid] = phib[tid];

    // layer-3 aggregation: thread per node (z1 fp32, offsets are fp16-row bytes -> >>4)
    {
        int   n   = nblk + tid;
        float dv  = degs[n];
        int   deg = (int)(dv + 0.5f) - 1;
        float acc = z1[n];
        const char* zb = (const char*)z1;
        const int* col = &g_colb[n * SLOT];
        int j = 0;
        for (; j + 4 <= deg; j += 4) {
            int4 a = *(const int4*)(col + j);
            float v0 = *(const float*)(zb + ((unsigned)a.x >> 4));
            float v1 = *(const float*)(zb + ((unsigned)a.y >> 4));
            float v2 = *(const float*)(zb + ((unsigned)a.z >> 4));
            float v3 = *(const float*)(zb + ((unsigned)a.w >> 4));
            acc += (v0 + v1) + (v2 + v3);
        }
        for (; j < deg; j++) acc += *(const float*)(zb + ((unsigned)col[j] >> 4));
        c3s[tid] = fast_tanh((acc + b3[0]) * fast_rcp(dv));
    }

    float psum = 0.f;

    for (int it = 0; it < 4; it++) {
        int nb = nblk + it * 64;
        __syncthreads();
        for (int i = tid; i < 64 * 32; i += 256) {
            int r = i >> 5, k = i & 31;
            Msm[r * 100 + k]      = c0[(nb + r) * 32 + k];
            Msm[r * 100 + 32 + k] = c1[(nb + r) * 32 + k];
            Msm[r * 100 + 64 + k] = c2[(nb + r) * 32 + k];
        }
        if (tid < 64) Msm[tid * 100 + 96] = c3s[it * 64 + tid];
        __syncthreads();

        float a0=0,a1=0,a2=0,a3=0,a4=0,a5=0,a6=0,a7=0;
        const float* Mr = &Msm[(wrp * 8) * 100];
        if (lane < KPHI) {
            const float* wrow = &Wt[lane * 100];
#pragma unroll 4
            for (int kk = 0; kk < 96; kk += 4) {
                float4 w  = *(const float4*)&wrow[kk];
                float4 m0 = *(const float4*)&Mr[0 * 100 + kk];
                float4 m1 = *(const float4*)&Mr[1 * 100 + kk];
                float4 m2 = *(const float4*)&Mr[2 * 100 + kk];
                float4 m3 = *(const float4*)&Mr[3 * 100 + kk];
                float4 m4 = *(const float4*)&Mr[4 * 100 + kk];
                float4 m5 = *(const float4*)&Mr[5 * 100 + kk];
                float4 m6 = *(const float4*)&Mr[6 * 100 + kk];
                float4 m7 = *(const float4*)&Mr[7 * 100 + kk];
                a0 += m0.x*w.x + m0.y*w.y + m0.z*w.z + m0.w*w.w;
                a1 += m1.x*w.x + m1.y*w.y + m1.z*w.z + m1.w*w.w;
                a2 += m2.x*w.x + m2.y*w.y + m2.z*w.z + m2.w*w.w;
                a3 += m3.x*w.x + m3.y*w.y + m3.z*w.z + m3.w*w.w;
                a4 += m4.x*w.x + m4.y*w.y + m4.z*w.z + m4.w*w.w;
                a5 += m5.x*w.x + m5.y*w.y + m5.z*w.z + m5.w*w.w;
                a6 += m6.x*w.x + m6.y*w.y + m6.z*w.z + m6.w*w.w;
                a7 += m7.x*w.x + m7.y*w.y + m7.z*w.z + m7.w*w.w;
            }
            float w96 = wrow[96];
            float bb  = bs[lane];
            a0 += Mr[0*100+96]*w96; a1 += Mr[1*100+96]*w96;
            a2 += Mr[2*100+96]*w96; a3 += Mr[3*100+96]*w96;
            a4 += Mr[4*100+96]*w96; a5 += Mr[5*100+96]*w96;
            a6 += Mr[6*100+96]*w96; a7 += Mr[7*100+96]*w96;
            psum += fmaxf(a0+bb,0.f)+fmaxf(a1+bb,0.f)+fmaxf(a2+bb,0.f)+fmaxf(a3+bb,0.f)
                  + fmaxf(a4+bb,0.f)+fmaxf(a5+bb,0.f)+fmaxf(a6+bb,0.f)+fmaxf(a7+bb,0.f);
        }
    }

    __syncthreads();
    red[wrp * 32 + lane] = psum;
    __syncthreads();
    if (tid < KPHI) {
        float s = 0.f;
#pragma unroll
        for (int q = 0; q < 8; q++) s += red[q * 32 + tid];
        atomicAdd(&g_gsum[(blockIdx.x >> 3) * 32 + tid], s);
    }
}

// ---------------- rho ----------------
__global__ void rho_kernel(const float* __restrict__ rhoW, const float* __restrict__ rhob,
                           float* __restrict__ out) {
    int t = threadIdx.x;
    int g = t >> 5, o = t & 31;
    float acc = rhob[o];
#pragma unroll
    for (int k = 0; k < KPHI; k++) acc += g_gsum[g * 32 + k] * rhoW[k * 32 + o];
    out[t] = acc;
}

// ---------------- launch ----------------
extern "C" void kernel_launch(void* const* d_in, const int* in_sizes, int n_in,
                              void* d_out, int out_size) {
    const float *node_feat, *node_degs;
    const int*   edge_index;
    const float *W0, *b0, *W1, *b1, *W2, *b2, *W3, *b3, *phiW, *phib, *rhoW, *rhob;

    if (in_sizes[2] == 2 * ECNT) {
        node_feat  = (const float*)d_in[0];
        node_degs  = (const float*)d_in[1];
        edge_index = (const int*)  d_in[2];
        W0 = (const float*)d_in[3];  b0 = (const float*)d_in[4];
        W1 = (const float*)d_in[5];  b1 = (const float*)d_in[6];
        W2 = (const float*)d_in[7];  b2 = (const float*)d_in[8];
        W3 = (const float*)d_in[9];  b3 = (const float*)d_in[10];
        phiW = (const float*)d_in[11]; phib = (const float*)d_in[12];
        rhoW = (const float*)d_in[13]; rhob = (const float*)d_in[14];
    } else {
        node_feat  = (const float*)d_in[0];
        node_degs  = (const float*)d_in[1];
        W0 = (const float*)d_in[2];  b0 = (const float*)d_in[3];
        W1 = (const float*)d_in[4];  b1 = (const float*)d_in[5];
        W2 = (const float*)d_in[6];  b2 = (const float*)d_in[7];
        W3 = (const float*)d_in[8];  b3 = (const float*)d_in[9];
        phiW = (const float*)d_in[10]; phib = (const float*)d_in[11];
        rhoW = (const float*)d_in[12]; rhob = (const float*)d_in[13];
        edge_index = (const int*)d_in[14];
    }

    __half2 *za, *zbuf;
    float *c0b, *c1b, *c2b, *z1b;
    cudaGetSymbolAddress((void**)&za,   g_zha);
    cudaGetSymbolAddress((void**)&zbuf, g_zhb);
    cudaGetSymbolAddress((void**)&c0b,  g_c0);
    cudaGetSymbolAddress((void**)&c1b,  g_c1);
    cudaGetSymbolAddress((void**)&c2b,  g_c2);
    cudaGetSymbolAddress((void**)&z1b,  g_z1);

    zero_kernel<<<NN / 256, 256>>>();
    fill_adj_kernel<<<ECNT / 512, 512>>>(edge_index);

    // layer 0: za = X @ W0 ; c0 = tanh((A za + za + b0)/deg) ; zb = c0 @ W1
    gemm128_kernel<<<NN / 32, 256>>>(node_feat, W0, za);
    agg_gemm32_kernel<<<NN / 16, 256>>>(za, b0, W1, node_degs, c0b, zbuf);
    // layer 1
    agg_gemm32_kernel<<<NN / 16, 256>>>(zbuf, b1, W2, node_degs, c1b, za);
    // layer 2 (epilogue 32->1)
    agg_gemm1_kernel<<<NN / 16, 256>>>(za, b2, W3, node_degs, c2b, z1b);
    // layer 3 + phi + per-graph sum
    agg1_phi_kernel<<<NN / 256, 256>>>(z1b, b3, node_degs, c0b, c1b, c2b, phiW, phib);
    // rho
    rho_kernel<<<1, 1024>>>(rhoW, rhob, (float*)d_out);
}

// round 4
// speedup vs baseline: 2.5782x; 1.0951x over previous
#include <cuda_runtime.h>
#include <cuda_fp16.h>
#include <stdint.h>

#define NN    65536
#define BG    32
#define NPG   2048
#define ECNT  1048576
#define FIN   128
#define DLAT  32
#define TOT   97
#define KPHI  30
#define SLOT  64

typedef unsigned long long ULL;

// ---------------- device scratch ----------------
__device__ int     g_cnt[NN];
__device__ int     g_colb[NN * SLOT];   // byte offsets: src*64
__device__ __half2 g_zha[NN * 16];
__device__ __half2 g_zhb[NN * 16];
__device__ float   g_c0 [NN * DLAT];
__device__ float   g_c1 [NN * DLAT];
__device__ float   g_c2 [NN * DLAT];
__device__ float   g_z1 [NN];
__device__ float   g_gsum[BG * 32];

// ---------------- f32x2 helpers ----------------
__device__ __forceinline__ ULL pk2(float x, float y) {
    ULL r; asm("mov.b64 %0,{%1,%2};" : "=l"(r) : "f"(x), "f"(y)); return r;
}
__device__ __forceinline__ void upk2(ULL v, float& x, float& y) {
    asm("mov.b64 {%0,%1},%2;" : "=f"(x), "=f"(y) : "l"(v));
}
__device__ __forceinline__ ULL ffma2(ULL a, ULL b, ULL c) {
    ULL d; asm("fma.rn.f32x2 %0,%1,%2,%3;" : "=l"(d) : "l"(a), "l"(b), "l"(c)); return d;
}

__device__ __forceinline__ float fast_tanh(float x) {
    float e;
    asm("ex2.approx.f32 %0, %1;" : "=f"(e) : "f"(x * 2.8853900817779268f));
    float r;
    asm("rcp.approx.f32 %0, %1;" : "=f"(r) : "f"(e + 1.0f));
    return 1.0f - 2.0f * r;
}
__device__ __forceinline__ float fast_rcp(float x) {
    float r;
    asm("rcp.approx.f32 %0, %1;" : "=f"(r) : "f"(x));
    return r;
}

// ---------------- init ----------------
__global__ void zero_kernel() {
    int t = blockIdx.x * blockDim.x + threadIdx.x;
    if (t < NN) g_cnt[t] = 0;
    if (t < BG * 32) g_gsum[t] = 0.0f;
}

// ---------------- adjacency fill ----------------
__global__ void fill_adj_kernel(const int* __restrict__ ei) {
    int e = blockIdx.x * blockDim.x + threadIdx.x;
    if (e >= ECNT) return;
    int s = ei[e];
    int d = ei[ECNT + e];
    int pos = atomicAdd(&g_cnt[d], 1);
    g_colb[d * SLOT + pos] = s * 64;
}

// ---------------- GEMM: Z[N,32](fp16) = X[N,128] @ W0[128,32] ----------------
// 256 threads, 64 rows/block (4 threads per row, 8 cols each), X read direct (warp-dedup)
__global__ void gemm128_kernel(const float* __restrict__ X, const float* __restrict__ W,
                               __half2* __restrict__ Z) {
    __shared__ float Ws[FIN * 32];
    int tid  = threadIdx.x;
    int base = blockIdx.x * 64;
    for (int i = tid; i < FIN * 32; i += 256) Ws[i] = W[i];
    __syncthreads();

    int row  = tid >> 2;
    int colg = (tid & 3) * 8;
    const float* xr = X + (base + row) * FIN;
    ULL a01 = 0, a23 = 0, a45 = 0, a67 = 0;
#pragma unroll 8
    for (int k4 = 0; k4 < FIN; k4 += 4) {
        float4 x4 = *(const float4*)&xr[k4];
#pragma unroll
        for (int q = 0; q < 4; q++) {
            float x = (q == 0) ? x4.x : (q == 1) ? x4.y : (q == 2) ? x4.z : x4.w;
            ULL x2 = pk2(x, x);
            const float* wr = &Ws[(k4 + q) * 32 + colg];
            float4 wA = *(const float4*)wr;
            float4 wB = *(const float4*)(wr + 4);
            a01 = ffma2(x2, pk2(wA.x, wA.y), a01);
            a23 = ffma2(x2, pk2(wA.z, wA.w), a23);
            a45 = ffma2(x2, pk2(wB.x, wB.y), a45);
            a67 = ffma2(x2, pk2(wB.z, wB.w), a67);
        }
    }
    float o0,o1,o2,o3,o4,o5,o6,o7;
    upk2(a01,o0,o1); upk2(a23,o2,o3); upk2(a45,o4,o5); upk2(a67,o6,o7);
    __half2 p0 = __floats2half2_rn(o0,o1), p1 = __floats2half2_rn(o2,o3);
    __half2 p2 = __floats2half2_rn(o4,o5), p3 = __floats2half2_rn(o6,o7);
    uint4 st;
    st.x = *(unsigned*)&p0; st.y = *(unsigned*)&p1;
    st.z = *(unsigned*)&p2; st.w = *(unsigned*)&p3;
    *(uint4*)((char*)Z + (size_t)(base + row) * 64 + colg * 2) = st;
}

// ---------------- gather: 8 lanes per node, 4 feats/lane via LDG.64 ----------------
__device__ __forceinline__ void gather4(const __half2* __restrict__ zh, int node,
                                        int deg, int l, __half2& A0, __half2& A1) {
    const char* zb   = (const char*)zh;
    unsigned    loff = (unsigned)(l * 8);
    const int*  col  = &g_colb[node * SLOT];
    uint2 s = *(const uint2*)(zb + (unsigned)(node * 64) + loff);
    __half2 a0 = *(__half2*)&s.x, a1 = *(__half2*)&s.y;
    __half2 b0 = __float2half2_rn(0.f), b1 = b0;
    int j = 0;
    for (; j + 4 <= deg; j += 4) {
        int4 o = *(const int4*)(col + j);
        uint2 u0 = *(const uint2*)(zb + (unsigned)o.x + loff);
        uint2 u1 = *(const uint2*)(zb + (unsigned)o.y + loff);
        uint2 u2 = *(const uint2*)(zb + (unsigned)o.z + loff);
        uint2 u3 = *(const uint2*)(zb + (unsigned)o.w + loff);
        a0 = __hadd2(a0, *(__half2*)&u0.x); a1 = __hadd2(a1, *(__half2*)&u0.y);
        b0 = __hadd2(b0, *(__half2*)&u1.x); b1 = __hadd2(b1, *(__half2*)&u1.y);
        a0 = __hadd2(a0, *(__half2*)&u2.x); a1 = __hadd2(a1, *(__half2*)&u2.y);
        b0 = __hadd2(b0, *(__half2*)&u3.x); b1 = __hadd2(b1, *(__half2*)&u3.y);
    }
    for (; j < deg; j++) {
        uint2 u = *(const uint2*)(zb + (unsigned)col[j] + loff);
        a0 = __hadd2(a0, *(__half2*)&u.x); a1 = __hadd2(a1, *(__half2*)&u.y);
    }
    A0 = __hadd2(a0, b0);
    A1 = __hadd2(a1, b1);
}

// ---------------- agg + tanh + fused 32->32 GEMM (f32x2 epilogue) ----------------
// 256 threads = 8 warps = 32 nodes/block
__global__ void agg_gemm32_kernel(const __half2* __restrict__ zh, const float* __restrict__ b,
                                  const float* __restrict__ Wn, const float* __restrict__ degs,
                                  float* __restrict__ c_out, __half2* __restrict__ z_out) {
    __shared__ float  Wsm[32 * 32];
    __shared__ float  bsm[32];
    __shared__ float2 hs[32][33];
    int tid = threadIdx.x;
    for (int i = tid; i < 1024; i += 256) Wsm[i] = Wn[i];
    if (tid < 32) bsm[tid] = b[tid];
    __syncthreads();

    int lane = tid & 31;
    int l    = lane & 7;
    int g    = lane >> 3;
    int node = (blockIdx.x * 8 + (tid >> 5)) * 4 + g;
    int slot = ((tid >> 5) << 2) + g;

    float dv  = degs[node];
    int   deg = (int)(dv + 0.5f) - 1;
    __half2 A0, A1;
    gather4(zh, node, deg, l, A0, A1);
    float rinv = fast_rcp(dv);
    float2 f0 = __half22float2(A0), f1 = __half22float2(A1);
    float4 bb = *(const float4*)&bsm[4 * l];
    float h0 = fast_tanh((f0.x + bb.x) * rinv);
    float h1 = fast_tanh((f0.y + bb.y) * rinv);
    float h2 = fast_tanh((f1.x + bb.z) * rinv);
    float h3 = fast_tanh((f1.y + bb.w) * rinv);
    *(float4*)&c_out[node * 32 + 4 * l] = make_float4(h0, h1, h2, h3);

    hs[slot][4 * l + 0] = make_float2(h0, h0);
    hs[slot][4 * l + 1] = make_float2(h1, h1);
    hs[slot][4 * l + 2] = make_float2(h2, h2);
    hs[slot][4 * l + 3] = make_float2(h3, h3);
    __syncwarp();

    ULL acc01 = 0, acc23 = 0;
#pragma unroll
    for (int k = 0; k < 32; k++) {
        float2 hk = hs[slot][k];
        float4 w4 = *(const float4*)&Wsm[k * 32 + 4 * l];
        ULL h2p = pk2(hk.x, hk.y);
        acc01 = ffma2(h2p, pk2(w4.x, w4.y), acc01);
        acc23 = ffma2(h2p, pk2(w4.z, w4.w), acc23);
    }
    float z0, z1v, z2, z3;
    upk2(acc01, z0, z1v); upk2(acc23, z2, z3);
    __half2 p0 = __floats2half2_rn(z0, z1v);
    __half2 p1 = __floats2half2_rn(z2, z3);
    uint2 st; st.x = *(unsigned*)&p0; st.y = *(unsigned*)&p1;
    *(uint2*)((char*)z_out + (size_t)node * 64 + l * 8) = st;
}

// ---------------- agg + tanh + fused 32->1 GEMM ----------------
__global__ void agg_gemm1_kernel(const __half2* __restrict__ zh, const float* __restrict__ b,
                                 const float* __restrict__ W3, const float* __restrict__ degs,
                                 float* __restrict__ c_out, float* __restrict__ z1_out) {
    __shared__ float w3s[32];
    __shared__ float bsm[32];
    int tid = threadIdx.x;
    if (tid < 32) { w3s[tid] = W3[tid]; bsm[tid] = b[tid]; }
    __syncthreads();

    int lane = tid & 31;
    int l    = lane & 7;
    int g    = lane >> 3;
    int node = (blockIdx.x * 8 + (tid >> 5)) * 4 + g;

    float dv  = degs[node];
    int   deg = (int)(dv + 0.5f) - 1;
    __half2 A0, A1;
    gather4(zh, node, deg, l, A0, A1);
    float rinv = fast_rcp(dv);
    float2 f0 = __half22float2(A0), f1 = __half22float2(A1);
    float4 bb = *(const float4*)&bsm[4 * l];
    float h0 = fast_tanh((f0.x + bb.x) * rinv);
    float h1 = fast_tanh((f0.y + bb.y) * rinv);
    float h2 = fast_tanh((f1.x + bb.z) * rinv);
    float h3 = fast_tanh((f1.y + bb.w) * rinv);
    *(float4*)&c_out[node * 32 + 4 * l] = make_float4(h0, h1, h2, h3);

    float4 w4 = *(const float4*)&w3s[4 * l];
    float v = h0 * w4.x + h1 * w4.y + h2 * w4.z + h3 * w4.w;
    v += __shfl_xor_sync(0xffffffffu, v, 1);
    v += __shfl_xor_sync(0xffffffffu, v, 2);
    v += __shfl_xor_sync(0xffffffffu, v, 4);
    if (l == 0) z1_out[node] = v;
}

// ---------------- fused: layer-3 agg + phi + per-graph reduce (f32x2) ----------------
__global__ void agg1_phi_kernel(const float* __restrict__ z1, const float* __restrict__ b3,
                                const float* __restrict__ degs,
                                const float* __restrict__ c0, const float* __restrict__ c1,
                                const float* __restrict__ c2,
                                const float* __restrict__ phiW, const float* __restrict__ phib) {
    __shared__ float Msm[64 * 100];
    __shared__ float Wt[30 * 100];
    __shared__ float c3s[256];
    __shared__ float bs[32];
    __shared__ float red[8 * 32];

    int tid  = threadIdx.x;
    int lane = tid & 31;
    int wrp  = tid >> 5;
    int nblk = blockIdx.x * 256;

    for (int i = tid; i < TOT * KPHI; i += 256) {
        int k = i / KPHI, o = i - k * KPHI;
        Wt[o * 100 + k] = phiW[i];
    }
    if (tid < KPHI) bs[tid] = phib[tid];

    {
        int   n   = nblk + tid;
        float dv  = degs[n];
        int   deg = (int)(dv + 0.5f) - 1;
        float acc = z1[n];
        const char* zb = (const char*)z1;
        const int* col = &g_colb[n * SLOT];
        int j = 0;
        for (; j + 4 <= deg; j += 4) {
            int4 a = *(const int4*)(col + j);
            float v0 = *(const float*)(zb + ((unsigned)a.x >> 4));
            float v1 = *(const float*)(zb + ((unsigned)a.y >> 4));
            float v2 = *(const float*)(zb + ((unsigned)a.z >> 4));
            float v3 = *(const float*)(zb + ((unsigned)a.w >> 4));
            acc += (v0 + v1) + (v2 + v3);
        }
        for (; j < deg; j++) acc += *(const float*)(zb + ((unsigned)col[j] >> 4));
        c3s[tid] = fast_tanh((acc + b3[0]) * fast_rcp(dv));
    }

    float psum = 0.f;

    for (int it = 0; it < 4; it++) {
        int nb = nblk + it * 64;
        __syncthreads();
        for (int i = tid; i < 64 * 32; i += 256) {
            int r = i >> 5, k = i & 31;
            Msm[r * 100 + k]      = c0[(nb + r) * 32 + k];
            Msm[r * 100 + 32 + k] = c1[(nb + r) * 32 + k];
            Msm[r * 100 + 64 + k] = c2[(nb + r) * 32 + k];
        }
        if (tid < 64) Msm[tid * 100 + 96] = c3s[it * 64 + tid];
        __syncthreads();

        const float* Mr = &Msm[(wrp * 8) * 100];
        if (lane < KPHI) {
            ULL a0=0,a1=0,a2=0,a3=0,a4=0,a5=0,a6=0,a7=0;
            const float* wrow = &Wt[lane * 100];
#pragma unroll 4
            for (int kk = 0; kk < 96; kk += 4) {
                float4 w = *(const float4*)&wrow[kk];
                ULL w01 = pk2(w.x, w.y), w23 = pk2(w.z, w.w);
                float4 m0 = *(const float4*)&Mr[0 * 100 + kk];
                float4 m1 = *(const float4*)&Mr[1 * 100 + kk];
                float4 m2 = *(const float4*)&Mr[2 * 100 + kk];
                float4 m3 = *(const float4*)&Mr[3 * 100 + kk];
                float4 m4 = *(const float4*)&Mr[4 * 100 + kk];
                float4 m5 = *(const float4*)&Mr[5 * 100 + kk];
                float4 m6 = *(const float4*)&Mr[6 * 100 + kk];
                float4 m7 = *(const float4*)&Mr[7 * 100 + kk];
                a0 = ffma2(pk2(m0.x,m0.y), w01, a0); a0 = ffma2(pk2(m0.z,m0.w), w23, a0);
                a1 = ffma2(pk2(m1.x,m1.y), w01, a1); a1 = ffma2(pk2(m1.z,m1.w), w23, a1);
                a2 = ffma2(pk2(m2.x,m2.y), w01, a2); a2 = ffma2(pk2(m2.z,m2.w), w23, a2);
                a3 = ffma2(pk2(m3.x,m3.y), w01, a3); a3 = ffma2(pk2(m3.z,m3.w), w23, a3);
                a4 = ffma2(pk2(m4.x,m4.y), w01, a4); a4 = ffma2(pk2(m4.z,m4.w), w23, a4);
                a5 = ffma2(pk2(m5.x,m5.y), w01, a5); a5 = ffma2(pk2(m5.z,m5.w), w23, a5);
                a6 = ffma2(pk2(m6.x,m6.y), w01, a6); a6 = ffma2(pk2(m6.z,m6.w), w23, a6);
                a7 = ffma2(pk2(m7.x,m7.y), w01, a7); a7 = ffma2(pk2(m7.z,m7.w), w23, a7);
            }
            float w96 = wrow[96];
            float bb  = bs[lane];
            float sx, sy, s;
            upk2(a0,sx,sy); s = sx+sy + Mr[0*100+96]*w96 + bb; psum += fmaxf(s,0.f);
            upk2(a1,sx,sy); s = sx+sy + Mr[1*100+96]*w96 + bb; psum += fmaxf(s,0.f);
            upk2(a2,sx,sy); s = sx+sy + Mr[2*100+96]*w96 + bb; psum += fmaxf(s,0.f);
            upk2(a3,sx,sy); s = sx+sy + Mr[3*100+96]*w96 + bb; psum += fmaxf(s,0.f);
            upk2(a4,sx,sy); s = sx+sy + Mr[4*100+96]*w96 + bb; psum += fmaxf(s,0.f);
            upk2(a5,sx,sy); s = sx+sy + Mr[5*100+96]*w96 + bb; psum += fmaxf(s,0.f);
            upk2(a6,sx,sy); s = sx+sy + Mr[6*100+96]*w96 + bb; psum += fmaxf(s,0.f);
            upk2(a7,sx,sy); s = sx+sy + Mr[7*100+96]*w96 + bb; psum += fmaxf(s,0.f);
        }
    }

    __syncthreads();
    red[wrp * 32 + lane] = psum;
    __syncthreads();
    if (tid < KPHI) {
        float s = 0.f;
#pragma unroll
        for (int q = 0; q < 8; q++) s += red[q * 32 + tid];
        atomicAdd(&g_gsum[(blockIdx.x >> 3) * 32 + tid], s);
    }
}

// ---------------- rho ----------------
__global__ void rho_kernel(const float* __restrict__ rhoW, const float* __restrict__ rhob,
                           float* __restrict__ out) {
    int t = threadIdx.x;
    int g = t >> 5, o = t & 31;
    float acc = rhob[o];
#pragma unroll
    for (int k = 0; k < KPHI; k++) acc += g_gsum[g * 32 + k] * rhoW[k * 32 + o];
    out[t] = acc;
}

// ---------------- launch ----------------
extern "C" void kernel_launch(void* const* d_in, const int* in_sizes, int n_in,
                              void* d_out, int out_size) {
    const float *node_feat, *node_degs;
    const int*   edge_index;
    const float *W0, *b0, *W1, *b1, *W2, *b2, *W3, *b3, *phiW, *phib, *rhoW, *rhob;

    if (in_sizes[2] == 2 * ECNT) {
        node_feat  = (const float*)d_in[0];
        node_degs  = (const float*)d_in[1];
        edge_index = (const int*)  d_in[2];
        W0 = (const float*)d_in[3];  b0 = (const float*)d_in[4];
        W1 = (const float*)d_in[5];  b1 = (const float*)d_in[6];
        W2 = (const float*)d_in[7];  b2 = (const float*)d_in[8];
        W3 = (const float*)d_in[9];  b3 = (const float*)d_in[10];
        phiW = (const float*)d_in[11]; phib = (const float*)d_in[12];
        rhoW = (const float*)d_in[13]; rhob = (const float*)d_in[14];
    } else {
        node_feat  = (const float*)d_in[0];
        node_degs  = (const float*)d_in[1];
        W0 = (const float*)d_in[2];  b0 = (const float*)d_in[3];
        W1 = (const float*)d_in[4];  b1 = (const float*)d_in[5];
        W2 = (const float*)d_in[6];  b2 = (const float*)d_in[7];
        W3 = (const float*)d_in[8];  b3 = (const float*)d_in[9];
        phiW = (const float*)d_in[10]; phib = (const float*)d_in[11];
        rhoW = (const float*)d_in[12]; rhob = (const float*)d_in[13];
        edge_index = (const int*)d_in[14];
    }

    __half2 *za, *zbuf;
    float *c0b, *c1b, *c2b, *z1b;
    cudaGetSymbolAddress((void**)&za,   g_zha);
    cudaGetSymbolAddress((void**)&zbuf, g_zhb);
    cudaGetSymbolAddress((void**)&c0b,  g_c0);
    cudaGetSymbolAddress((void**)&c1b,  g_c1);
    cudaGetSymbolAddress((void**)&c2b,  g_c2);
    cudaGetSymbolAddress((void**)&z1b,  g_z1);

    zero_kernel<<<NN / 256, 256>>>();
    fill_adj_kernel<<<ECNT / 512, 512>>>(edge_index);

    gemm128_kernel<<<NN / 64, 256>>>(node_feat, W0, za);
    agg_gemm32_kernel<<<NN / 32, 256>>>(za, b0, W1, node_degs, c0b, zbuf);
    agg_gemm32_kernel<<<NN / 32, 256>>>(zbuf, b1, W2, node_degs, c1b, za);
    agg_gemm1_kernel<<<NN / 32, 256>>>(za, b2, W3, node_degs, c2b, z1b);
    agg1_phi_kernel<<<NN / 256, 256>>>(z1b, b3, node_degs, c0b, c1b, c2b, phiW, phib);
    rho_kernel<<<1, 1024>>>(rhoW, rhob, (float*)d_out);
}

// round 5
// speedup vs baseline: 2.6112x; 1.0128x over previous
#include <cuda_runtime.h>
#include <cuda_fp16.h>
#include <stdint.h>

#define NN    65536
#define BG    32
#define NPG   2048
#define ECNT  1048576
#define FIN   128
#define DLAT  32
#define TOT   97
#define KPHI  30
#define SLOT  64

typedef unsigned long long ULL;

// ---------------- device scratch ----------------
__device__ int     g_cnt[NN];
__device__ int     g_colb[NN * SLOT + 16];   // byte offsets src*64, +16 pad for batch read
__device__ __half2 g_zha[NN * 16 + 16];      // +1 guard row (zeros)
__device__ __half2 g_zhb[NN * 16 + 16];
__device__ float   g_c0 [NN * DLAT];
__device__ float   g_c1 [NN * DLAT];
__device__ float   g_c2 [NN * DLAT];
__device__ float   g_z1 [NN + 16];           // +guard (zeros)
__device__ float   g_gsum[BG * 32];

// ---------------- f32x2 helpers ----------------
__device__ __forceinline__ ULL pk2(float x, float y) {
    ULL r; asm("mov.b64 %0,{%1,%2};" : "=l"(r) : "f"(x), "f"(y)); return r;
}
__device__ __forceinline__ void upk2(ULL v, float& x, float& y) {
    asm("mov.b64 {%0,%1},%2;" : "=f"(x), "=f"(y) : "l"(v));
}
__device__ __forceinline__ ULL ffma2(ULL a, ULL b, ULL c) {
    ULL d; asm("fma.rn.f32x2 %0,%1,%2,%3;" : "=l"(d) : "l"(a), "l"(b), "l"(c)); return d;
}

__device__ __forceinline__ float fast_tanh(float x) {
    float e;
    asm("ex2.approx.f32 %0, %1;" : "=f"(e) : "f"(x * 2.8853900817779268f));
    float r;
    asm("rcp.approx.f32 %0, %1;" : "=f"(r) : "f"(e + 1.0f));
    return 1.0f - 2.0f * r;
}
__device__ __forceinline__ float fast_rcp(float x) {
    float r;
    asm("rcp.approx.f32 %0, %1;" : "=f"(r) : "f"(x));
    return r;
}

// ---------------- init ----------------
__global__ void zero_kernel() {
    int t = blockIdx.x * blockDim.x + threadIdx.x;
    if (t < NN) g_cnt[t] = 0;
    if (t < BG * 32) g_gsum[t] = 0.0f;
    if (t < 16) {                       // guard rows
        g_zha[NN * 16 + t] = __float2half2_rn(0.f);
        g_zhb[NN * 16 + t] = __float2half2_rn(0.f);
        g_z1[NN + t] = 0.0f;
    }
}

// ---------------- adjacency fill ----------------
__global__ void fill_adj_kernel(const int* __restrict__ ei) {
    int e = blockIdx.x * blockDim.x + threadIdx.x;
    if (e >= ECNT) return;
    int s = ei[e];
    int d = ei[ECNT + e];
    int pos = atomicAdd(&g_cnt[d], 1);
    g_colb[d * SLOT + pos] = s * 64;
}

// ---------------- GEMM: Z[N,32](fp16) = X[N,128] @ W0[128,32] ----------------
__global__ void gemm128_kernel(const float* __restrict__ X, const float* __restrict__ W,
                               __half2* __restrict__ Z) {
    __shared__ float Ws[FIN * 32];
    int tid  = threadIdx.x;
    int base = blockIdx.x * 64;
    for (int i = tid; i < FIN * 32; i += 256) Ws[i] = W[i];
    __syncthreads();

    int row  = tid >> 2;
    int colg = (tid & 3) * 8;
    const float* xr = X + (base + row) * FIN;
    ULL a01 = 0, a23 = 0, a45 = 0, a67 = 0;
#pragma unroll 8
    for (int k4 = 0; k4 < FIN; k4 += 4) {
        float4 x4 = *(const float4*)&xr[k4];
#pragma unroll
        for (int q = 0; q < 4; q++) {
            float x = (q == 0) ? x4.x : (q == 1) ? x4.y : (q == 2) ? x4.z : x4.w;
            ULL x2 = pk2(x, x);
            const float* wr = &Ws[(k4 + q) * 32 + colg];
            float4 wA = *(const float4*)wr;
            float4 wB = *(const float4*)(wr + 4);
            a01 = ffma2(x2, pk2(wA.x, wA.y), a01);
            a23 = ffma2(x2, pk2(wA.z, wA.w), a23);
            a45 = ffma2(x2, pk2(wB.x, wB.y), a45);
            a67 = ffma2(x2, pk2(wB.z, wB.w), a67);
        }
    }
    float o0,o1,o2,o3,o4,o5,o6,o7;
    upk2(a01,o0,o1); upk2(a23,o2,o3); upk2(a45,o4,o5); upk2(a67,o6,o7);
    __half2 p0 = __floats2half2_rn(o0,o1), p1 = __floats2half2_rn(o2,o3);
    __half2 p2 = __floats2half2_rn(o4,o5), p3 = __floats2half2_rn(o6,o7);
    uint4 st;
    st.x = *(unsigned*)&p0; st.y = *(unsigned*)&p1;
    st.z = *(unsigned*)&p2; st.w = *(unsigned*)&p3;
    *(uint4*)((char*)Z + (size_t)(base + row) * 64 + colg * 2) = st;
}

// ---------------- gather: 8 lanes/node, batch-16 predicated loads (MLP=16) ----------
__device__ __forceinline__ void gather4(const __half2* __restrict__ zh, int node,
                                        int deg, int l, __half2& A0, __half2& A1) {
    const char* zb   = (const char*)zh;
    unsigned    loff = (unsigned)(l * 8);
    const int*  col  = &g_colb[node * SLOT];
    const unsigned guard = (unsigned)(NN * 64);
    uint2 sv = *(const uint2*)(zb + (unsigned)(node * 64) + loff);
    __half2 zz = __float2half2_rn(0.f);
    __half2 p0[4], p1[4];
    p0[0] = *(__half2*)&sv.x; p1[0] = *(__half2*)&sv.y;
    p0[1] = zz; p0[2] = zz; p0[3] = zz;
    p1[1] = zz; p1[2] = zz; p1[3] = zz;

    for (int jb = 0; jb < deg; jb += 16) {
        int4 c0 = *(const int4*)(col + jb);
        int4 c1 = *(const int4*)(col + jb + 4);
        int4 c2 = *(const int4*)(col + jb + 8);
        int4 c3 = *(const int4*)(col + jb + 12);
        unsigned o[16];
        o[0]=(unsigned)c0.x; o[1]=(unsigned)c0.y; o[2]=(unsigned)c0.z; o[3]=(unsigned)c0.w;
        o[4]=(unsigned)c1.x; o[5]=(unsigned)c1.y; o[6]=(unsigned)c1.z; o[7]=(unsigned)c1.w;
        o[8]=(unsigned)c2.x; o[9]=(unsigned)c2.y; o[10]=(unsigned)c2.z; o[11]=(unsigned)c2.w;
        o[12]=(unsigned)c3.x; o[13]=(unsigned)c3.y; o[14]=(unsigned)c3.z; o[15]=(unsigned)c3.w;
#pragma unroll
        for (int i = 0; i < 16; i++)
            if (jb + i >= deg) o[i] = guard;
        uint2 u[16];
#pragma unroll
        for (int i = 0; i < 16; i++)
            u[i] = *(const uint2*)(zb + o[i] + loff);
#pragma unroll
        for (int i = 0; i < 16; i++) {
            p0[i & 3] = __hadd2(p0[i & 3], *(__half2*)&u[i].x);
            p1[i & 3] = __hadd2(p1[i & 3], *(__half2*)&u[i].y);
        }
    }
    A0 = __hadd2(__hadd2(p0[0], p0[1]), __hadd2(p0[2], p0[3]));
    A1 = __hadd2(__hadd2(p1[0], p1[1]), __hadd2(p1[2], p1[3]));
}

// ---------------- agg + tanh + fused 32->32 GEMM ----------------
__global__ void agg_gemm32_kernel(const __half2* __restrict__ zh, const float* __restrict__ b,
                                  const float* __restrict__ Wn, const float* __restrict__ degs,
                                  float* __restrict__ c_out, __half2* __restrict__ z_out) {
    __shared__ float  Wsm[32 * 32];
    __shared__ float  bsm[32];
    __shared__ float2 hs[32][33];
    int tid = threadIdx.x;
    for (int i = tid; i < 1024; i += 256) Wsm[i] = Wn[i];
    if (tid < 32) bsm[tid] = b[tid];
    __syncthreads();

    int lane = tid & 31;
    int l    = lane & 7;
    int g    = lane >> 3;
    int node = (blockIdx.x * 8 + (tid >> 5)) * 4 + g;
    int slot = ((tid >> 5) << 2) + g;

    float dv  = degs[node];
    int   deg = (int)(dv + 0.5f) - 1;
    __half2 A0, A1;
    gather4(zh, node, deg, l, A0, A1);
    float rinv = fast_rcp(dv);
    float2 f0 = __half22float2(A0), f1 = __half22float2(A1);
    float4 bb = *(const float4*)&bsm[4 * l];
    float h0 = fast_tanh((f0.x + bb.x) * rinv);
    float h1 = fast_tanh((f0.y + bb.y) * rinv);
    float h2 = fast_tanh((f1.x + bb.z) * rinv);
    float h3 = fast_tanh((f1.y + bb.w) * rinv);
    *(float4*)&c_out[node * 32 + 4 * l] = make_float4(h0, h1, h2, h3);

    hs[slot][4 * l + 0] = make_float2(h0, h0);
    hs[slot][4 * l + 1] = make_float2(h1, h1);
    hs[slot][4 * l + 2] = make_float2(h2, h2);
    hs[slot][4 * l + 3] = make_float2(h3, h3);
    __syncwarp();

    ULL acc01 = 0, acc23 = 0;
#pragma unroll
    for (int k = 0; k < 32; k++) {
        float2 hk = hs[slot][k];
        float4 w4 = *(const float4*)&Wsm[k * 32 + 4 * l];
        ULL h2p = pk2(hk.x, hk.y);
        acc01 = ffma2(h2p, pk2(w4.x, w4.y), acc01);
        acc23 = ffma2(h2p, pk2(w4.z, w4.w), acc23);
    }
    float z0, z1v, z2, z3;
    upk2(acc01, z0, z1v); upk2(acc23, z2, z3);
    __half2 p0 = __floats2half2_rn(z0, z1v);
    __half2 p1 = __floats2half2_rn(z2, z3);
    uint2 st; st.x = *(unsigned*)&p0; st.y = *(unsigned*)&p1;
    *(uint2*)((char*)z_out + (size_t)node * 64 + l * 8) = st;
}

// ---------------- agg + tanh + fused 32->1 GEMM ----------------
__global__ void agg_gemm1_kernel(const __half2* __restrict__ zh, const float* __restrict__ b,
                                 const float* __restrict__ W3, const float* __restrict__ degs,
                                 float* __restrict__ c_out, float* __restrict__ z1_out) {
    __shared__ float w3s[32];
    __shared__ float bsm[32];
    int tid = threadIdx.x;
    if (tid < 32) { w3s[tid] = W3[tid]; bsm[tid] = b[tid]; }
    __syncthreads();

    int lane = tid & 31;
    int l    = lane & 7;
    int g    = lane >> 3;
    int node = (blockIdx.x * 8 + (tid >> 5)) * 4 + g;

    float dv  = degs[node];
    int   deg = (int)(dv + 0.5f) - 1;
    __half2 A0, A1;
    gather4(zh, node, deg, l, A0, A1);
    float rinv = fast_rcp(dv);
    float2 f0 = __half22float2(A0), f1 = __half22float2(A1);
    float4 bb = *(const float4*)&bsm[4 * l];
    float h0 = fast_tanh((f0.x + bb.x) * rinv);
    float h1 = fast_tanh((f0.y + bb.y) * rinv);
    float h2 = fast_tanh((f1.x + bb.z) * rinv);
    float h3 = fast_tanh((f1.y + bb.w) * rinv);
    *(float4*)&c_out[node * 32 + 4 * l] = make_float4(h0, h1, h2, h3);

    float4 w4 = *(const float4*)&w3s[4 * l];
    float v = h0 * w4.x + h1 * w4.y + h2 * w4.z + h3 * w4.w;
    v += __shfl_xor_sync(0xffffffffu, v, 1);
    v += __shfl_xor_sync(0xffffffffu, v, 2);
    v += __shfl_xor_sync(0xffffffffu, v, 4);
    if (l == 0) z1_out[node] = v;
}

// ---------------- fused: layer-3 agg + phi + per-graph reduce ----------------
__global__ void agg1_phi_kernel(const float* __restrict__ z1, const float* __restrict__ b3,
                                const float* __restrict__ degs,
                                const float* __restrict__ c0, const float* __restrict__ c1,
                                const float* __restrict__ c2,
                                const float* __restrict__ phiW, const float* __restrict__ phib) {
    __shared__ float Msm[64 * 100];
    __shared__ float Wt[30 * 100];
    __shared__ float c3s[256];
    __shared__ float bs[32];
    __shared__ float red[8 * 32];

    int tid  = threadIdx.x;
    int lane = tid & 31;
    int wrp  = tid >> 5;
    int nblk = blockIdx.x * 256;

    for (int i = tid; i < TOT * KPHI; i += 256) {
        int k = i / KPHI, o = i - k * KPHI;
        Wt[o * 100 + k] = phiW[i];
    }
    if (tid < KPHI) bs[tid] = phib[tid];

    // layer-3 scalar gather, batch-16 predicated
    {
        int   n   = nblk + tid;
        float dv  = degs[n];
        int   deg = (int)(dv + 0.5f) - 1;
        const char* zb = (const char*)z1;
        const int* col = &g_colb[n * SLOT];
        const unsigned guard = (unsigned)(NN * 64);
        float p[4] = {z1[n], 0.f, 0.f, 0.f};
        for (int jb = 0; jb < deg; jb += 16) {
            int4 c0v = *(const int4*)(col + jb);
            int4 c1v = *(const int4*)(col + jb + 4);
            int4 c2v = *(const int4*)(col + jb + 8);
            int4 c3v = *(const int4*)(col + jb + 12);
            unsigned o[16];
            o[0]=(unsigned)c0v.x; o[1]=(unsigned)c0v.y; o[2]=(unsigned)c0v.z; o[3]=(unsigned)c0v.w;
            o[4]=(unsigned)c1v.x; o[5]=(unsigned)c1v.y; o[6]=(unsigned)c1v.z; o[7]=(unsigned)c1v.w;
            o[8]=(unsigned)c2v.x; o[9]=(unsigned)c2v.y; o[10]=(unsigned)c2v.z; o[11]=(unsigned)c2v.w;
            o[12]=(unsigned)c3v.x; o[13]=(unsigned)c3v.y; o[14]=(unsigned)c3v.z; o[15]=(unsigned)c3v.w;
#pragma unroll
            for (int i = 0; i < 16; i++)
                if (jb + i >= deg) o[i] = guard;
            float v[16];
#pragma unroll
            for (int i = 0; i < 16; i++)
                v[i] = *(const float*)(zb + (o[i] >> 4));
#pragma unroll
            for (int i = 0; i < 16; i++) p[i & 3] += v[i];
        }
        c3s[tid] = fast_tanh(((p[0] + p[1]) + (p[2] + p[3]) + b3[0]) * fast_rcp(dv));
    }

    float psum = 0.f;

    for (int it = 0; it < 4; it++) {
        int nb = nblk + it * 64;
        __syncthreads();
        for (int i = tid; i < 64 * 32; i += 256) {
            int r = i >> 5, k = i & 31;
            Msm[r * 100 + k]      = c0[(nb + r) * 32 + k];
            Msm[r * 100 + 32 + k] = c1[(nb + r) * 32 + k];
            Msm[r * 100 + 64 + k] = c2[(nb + r) * 32 + k];
        }
        if (tid < 64) Msm[tid * 100 + 96] = c3s[it * 64 + tid];
        __syncthreads();

        const float* Mr = &Msm[(wrp * 8) * 100];
        if (lane < KPHI) {
            ULL a0=0,a1=0,a2=0,a3=0,a4=0,a5=0,a6=0,a7=0;
            const float* wrow = &Wt[lane * 100];
#pragma unroll 4
            for (int kk = 0; kk < 96; kk += 4) {
                float4 w = *(const float4*)&wrow[kk];
                ULL w01 = pk2(w.x, w.y), w23 = pk2(w.z, w.w);
                float4 m0 = *(const float4*)&Mr[0 * 100 + kk];
                float4 m1 = *(const float4*)&Mr[1 * 100 + kk];
                float4 m2 = *(const float4*)&Mr[2 * 100 + kk];
                float4 m3 = *(const float4*)&Mr[3 * 100 + kk];
                float4 m4 = *(const float4*)&Mr[4 * 100 + kk];
                float4 m5 = *(const float4*)&Mr[5 * 100 + kk];
                float4 m6 = *(const float4*)&Mr[6 * 100 + kk];
                float4 m7 = *(const float4*)&Mr[7 * 100 + kk];
                a0 = ffma2(pk2(m0.x,m0.y), w01, a0); a0 = ffma2(pk2(m0.z,m0.w), w23, a0);
                a1 = ffma2(pk2(m1.x,m1.y), w01, a1); a1 = ffma2(pk2(m1.z,m1.w), w23, a1);
                a2 = ffma2(pk2(m2.x,m2.y), w01, a2); a2 = ffma2(pk2(m2.z,m2.w), w23, a2);
                a3 = ffma2(pk2(m3.x,m3.y), w01, a3); a3 = ffma2(pk2(m3.z,m3.w), w23, a3);
                a4 = ffma2(pk2(m4.x,m4.y), w01, a4); a4 = ffma2(pk2(m4.z,m4.w), w23, a4);
                a5 = ffma2(pk2(m5.x,m5.y), w01, a5); a5 = ffma2(pk2(m5.z,m5.w), w23, a5);
                a6 = ffma2(pk2(m6.x,m6.y), w01, a6); a6 = ffma2(pk2(m6.z,m6.w), w23, a6);
                a7 = ffma2(pk2(m7.x,m7.y), w01, a7); a7 = ffma2(pk2(m7.z,m7.w), w23, a7);
            }
            float w96 = wrow[96];
            float bb  = bs[lane];
            float sx, sy, s;
            upk2(a0,sx,sy); s = sx+sy + Mr[0*100+96]*w96 + bb; psum += fmaxf(s,0.f);
            upk2(a1,sx,sy); s = sx+sy + Mr[1*100+96]*w96 + bb; psum += fmaxf(s,0.f);
            upk2(a2,sx,sy); s = sx+sy + Mr[2*100+96]*w96 + bb; psum += fmaxf(s,0.f);
            upk2(a3,sx,sy); s = sx+sy + Mr[3*100+96]*w96 + bb; psum += fmaxf(s,0.f);
            upk2(a4,sx,sy); s = sx+sy + Mr[4*100+96]*w96 + bb; psum += fmaxf(s,0.f);
            upk2(a5,sx,sy); s = sx+sy + Mr[5*100+96]*w96 + bb; psum += fmaxf(s,0.f);
            upk2(a6,sx,sy); s = sx+sy + Mr[6*100+96]*w96 + bb; psum += fmaxf(s,0.f);
            upk2(a7,sx,sy); s = sx+sy + Mr[7*100+96]*w96 + bb; psum += fmaxf(s,0.f);
        }
    }

    __syncthreads();
    red[wrp * 32 + lane] = psum;
    __syncthreads();
    if (tid < KPHI) {
        float s = 0.f;
#pragma unroll
        for (int q = 0; q < 8; q++) s += red[q * 32 + tid];
        atomicAdd(&g_gsum[(blockIdx.x >> 3) * 32 + tid], s);
    }
}

// ---------------- rho ----------------
__global__ void rho_kernel(const float* __restrict__ rhoW, const float* __restrict__ rhob,
                           float* __restrict__ out) {
    int t = threadIdx.x;
    int g = t >> 5, o = t & 31;
    float acc = rhob[o];
#pragma unroll
    for (int k = 0; k < KPHI; k++) acc += g_gsum[g * 32 + k] * rhoW[k * 32 + o];
    out[t] = acc;
}

// ---------------- launch ----------------
extern "C" void kernel_launch(void* const* d_in, const int* in_sizes, int n_in,
                              void* d_out, int out_size) {
    const float *node_feat, *node_degs;
    const int*   edge_index;
    const float *W0, *b0, *W1, *b1, *W2, *b2, *W3, *b3, *phiW, *phib, *rhoW, *rhob;

    if (in_sizes[2] == 2 * ECNT) {
        node_feat  = (const float*)d_in[0];
        node_degs  = (const float*)d_in[1];
        edge_index = (const int*)  d_in[2];
        W0 = (const float*)d_in[3];  b0 = (const float*)d_in[4];
        W1 = (const float*)d_in[5];  b1 = (const float*)d_in[6];
        W2 = (const float*)d_in[7];  b2 = (const float*)d_in[8];
        W3 = (const float*)d_in[9];  b3 = (const float*)d_in[10];
        phiW = (const float*)d_in[11]; phib = (const float*)d_in[12];
        rhoW = (const float*)d_in[13]; rhob = (const float*)d_in[14];
    } else {
        node_feat  = (const float*)d_in[0];
        node_degs  = (const float*)d_in[1];
        W0 = (const float*)d_in[2];  b0 = (const float*)d_in[3];
        W1 = (const float*)d_in[4];  b1 = (const float*)d_in[5];
        W2 = (const float*)d_in[6];  b2 = (const float*)d_in[7];
        W3 = (const float*)d_in[8];  b3 = (const float*)d_in[9];
        phiW = (const float*)d_in[10]; phib = (const float*)d_in[11];
        rhoW = (const float*)d_in[12]; rhob = (const float*)d_in[13];
        edge_index = (const int*)d_in[14];
    }

    __half2 *za, *zbuf;
    float *c0b, *c1b, *c2b, *z1b;
    cudaGetSymbolAddress((void**)&za,   g_zha);
    cudaGetSymbolAddress((void**)&zbuf, g_zhb);
    cudaGetSymbolAddress((void**)&c0b,  g_c0);
    cudaGetSymbolAddress((void**)&c1b,  g_c1);
    cudaGetSymbolAddress((void**)&c2b,  g_c2);
    cudaGetSymbolAddress((void**)&z1b,  g_z1);

    zero_kernel<<<NN / 256, 256>>>();
    fill_adj_kernel<<<ECNT / 512, 512>>>(edge_index);

    gemm128_kernel<<<NN / 64, 256>>>(node_feat, W0, za);
    agg_gemm32_kernel<<<NN / 32, 256>>>(za, b0, W1, node_degs, c0b, zbuf);
    agg_gemm32_kernel<<<NN / 32, 256>>>(zbuf, b1, W2, node_degs, c1b, za);
    agg_gemm1_kernel<<<NN / 32, 256>>>(za, b2, W3, node_degs, c2b, z1b);
    agg1_phi_kernel<<<NN / 256, 256>>>(z1b, b3, node_degs, c0b, c1b, c2b, phiW, phib);
    rho_kernel<<<1, 1024>>>(rhoW, rhob, (float*)d_out);
}